// round 1
// baseline (speedup 1.0000x reference)
#include <cuda_runtime.h>

#define NCOEF 1001            // degree 1000 -> 1001 coefficients
#define THREADS_PER_BLOCK 128
#define ELEMS_PER_THREAD 4    // two f32x2 Horner chains

// ---- packed f32x2 helpers (Blackwell FFMA2 path) ----
__device__ __forceinline__ unsigned long long pk2(float a, float b) {
    unsigned long long r;
    asm("mov.b64 %0, {%1, %2};" : "=l"(r) : "f"(a), "f"(b));
    return r;
}
__device__ __forceinline__ unsigned long long ffma2(unsigned long long a,
                                                    unsigned long long b,
                                                    unsigned long long c) {
    unsigned long long d;
    asm("fma.rn.f32x2 %0, %1, %2, %3;" : "=l"(d) : "l"(a), "l"(b), "l"(c));
    return d;
}

__global__ __launch_bounds__(THREADS_PER_BLOCK)
void poly_horner_kernel(const float* __restrict__ x,
                        const float* __restrict__ w,
                        float* __restrict__ out) {
    // w duplicated into (w_i, w_i) pairs so FFMA2 addend is a ready register
    // pair straight out of LDS.128 (no pack MOVs in the hot loop).
    __shared__ __align__(16) float2 w2s[NCOEF + 1];

    for (int i = threadIdx.x; i < NCOEF; i += THREADS_PER_BLOCK) {
        float v = w[i];
        w2s[i] = make_float2(v, v);
    }
    __syncthreads();

    const int t = blockIdx.x * THREADS_PER_BLOCK + threadIdx.x;
    const float4 xv = reinterpret_cast<const float4*>(x)[t];
    const unsigned long long x01 = pk2(xv.x, xv.y);
    const unsigned long long x23 = pk2(xv.z, xv.w);

    // Horner init with highest coefficient w[1000]
    const float wtop = w2s[NCOEF - 1].x;
    unsigned long long y01 = pk2(wtop, wtop);
    unsigned long long y23 = y01;

    // Remaining 1000 coefficients, 999 .. 0, in 125 groups of 8.
    // p points at the float4 covering (w2s[998], w2s[999]).
    const float4* p = reinterpret_cast<const float4*>(w2s) + (NCOEF - 1) / 2 - 1;

    #pragma unroll 1
    for (int it = 0; it < (NCOEF - 1) / 8; ++it) {
        // prefetch 4x LDS.128 -> coefficients jb+7 .. jb (jb = 992 - 8*it)
        const float4 a = p[0];    // (w[jb+6],w[jb+6],w[jb+7],w[jb+7])
        const float4 b = p[-1];   // jb+4, jb+5
        const float4 c = p[-2];   // jb+2, jb+3
        const float4 d = p[-3];   // jb+0, jb+1
        p -= 4;

        unsigned long long wv;
        wv = pk2(a.z, a.w); y01 = ffma2(y01, x01, wv); y23 = ffma2(y23, x23, wv);
        wv = pk2(a.x, a.y); y01 = ffma2(y01, x01, wv); y23 = ffma2(y23, x23, wv);
        wv = pk2(b.z, b.w); y01 = ffma2(y01, x01, wv); y23 = ffma2(y23, x23, wv);
        wv = pk2(b.x, b.y); y01 = ffma2(y01, x01, wv); y23 = ffma2(y23, x23, wv);
        wv = pk2(c.z, c.w); y01 = ffma2(y01, x01, wv); y23 = ffma2(y23, x23, wv);
        wv = pk2(c.x, c.y); y01 = ffma2(y01, x01, wv); y23 = ffma2(y23, x23, wv);
        wv = pk2(d.z, d.w); y01 = ffma2(y01, x01, wv); y23 = ffma2(y23, x23, wv);
        wv = pk2(d.x, d.y); y01 = ffma2(y01, x01, wv); y23 = ffma2(y23, x23, wv);
    }

    float r0, r1, r2, r3;
    asm("mov.b64 {%0, %1}, %2;" : "=f"(r0), "=f"(r1) : "l"(y01));
    asm("mov.b64 {%0, %1}, %2;" : "=f"(r2), "=f"(r3) : "l"(y23));
    reinterpret_cast<float4*>(out)[t] = make_float4(r0, r1, r2, r3);
}

extern "C" void kernel_launch(void* const* d_in, const int* in_sizes, int n_in,
                              void* d_out, int out_size) {
    const float* x = (const float*)d_in[0];   // (512, 1024) fp32
    const float* w = (const float*)d_in[1];   // (1001,) fp32
    float* out = (float*)d_out;               // (512, 1024) fp32

    const int n4 = out_size / ELEMS_PER_THREAD;          // 131072 threads
    const int grid = n4 / THREADS_PER_BLOCK;             // 1024 blocks
    poly_horner_kernel<<<grid, THREADS_PER_BLOCK>>>(x, w, out);
}

// round 3
// speedup vs baseline: 1.0616x; 1.0616x over previous
#include <cuda_runtime.h>

#define NCOEF 1001            // degree 1000 -> 1001 coefficients
#define THREADS_PER_BLOCK 128
#define ELEMS_PER_THREAD 4    // two f32x2 Horner chains per thread

typedef unsigned long long u64;

__device__ __forceinline__ u64 pk2(float a, float b) {
    u64 r;
    asm("mov.b64 %0, {%1, %2};" : "=l"(r) : "f"(a), "f"(b));
    return r;
}
__device__ __forceinline__ u64 ffma2(u64 a, u64 b, u64 c) {
    u64 d;
    asm("fma.rn.f32x2 %0, %1, %2, %3;" : "=l"(d) : "l"(a), "l"(b), "l"(c));
    return d;
}

__global__ __launch_bounds__(THREADS_PER_BLOCK)
void poly_horner_kernel(const float* __restrict__ x,
                        const float* __restrict__ w,
                        float* __restrict__ out) {
    // w duplicated into (w_i, w_i) pairs. Loaded in the hot loop as
    // ulonglong2 (ld.shared.v2.u64): each 16B LDS yields TWO ready 64-bit
    // FFMA2 c-operands in aligned register pairs -> zero packing MOVs.
    __shared__ __align__(16) float2 w2s[NCOEF + 1];

    const int t = blockIdx.x * THREADS_PER_BLOCK + threadIdx.x;
    const float4 xv = reinterpret_cast<const float4*>(x)[t];   // issue LDG early

    for (int i = threadIdx.x; i < NCOEF; i += THREADS_PER_BLOCK) {
        float v = w[i];
        w2s[i] = make_float2(v, v);
    }
    __syncthreads();

    const u64 x01 = pk2(xv.x, xv.y);
    const u64 x23 = pk2(xv.z, xv.w);

    // Horner init with highest coefficient w[1000]
    const float wtop = w2s[NCOEF - 1].x;
    u64 y01 = pk2(wtop, wtop);
    u64 y23 = y01;

    // Remaining 1000 coefficients (999..0) = 500 ulonglong2 elements:
    // element k covers coeffs (2k, 2k+1). Start at k=499 -> coeffs (998,999).
    // Budget: prologue loads 4 + 124 iterations x 4 = 500 elements exactly.
    const ulonglong2* p = reinterpret_cast<const ulonglong2*>(w2s) + 499;

    // Pipeline prologue: preload group 0 (coeffs 999..992)
    ulonglong2 A = p[0];     // {998, 999}
    ulonglong2 B = p[-1];    // {996, 997}
    ulonglong2 C = p[-2];    // {994, 995}
    ulonglong2 D = p[-3];    // {992, 993}
    p -= 4;

    #pragma unroll 2
    for (int it = 0; it < 124; ++it) {
        // prefetch next group while current one is consumed (hides LDS lat)
        const ulonglong2 A2 = p[0];
        const ulonglong2 B2 = p[-1];
        const ulonglong2 C2 = p[-2];
        const ulonglong2 D2 = p[-3];
        p -= 4;

        y01 = ffma2(y01, x01, A.y); y23 = ffma2(y23, x23, A.y);
        y01 = ffma2(y01, x01, A.x); y23 = ffma2(y23, x23, A.x);
        y01 = ffma2(y01, x01, B.y); y23 = ffma2(y23, x23, B.y);
        y01 = ffma2(y01, x01, B.x); y23 = ffma2(y23, x23, B.x);
        y01 = ffma2(y01, x01, C.y); y23 = ffma2(y23, x23, C.y);
        y01 = ffma2(y01, x01, C.x); y23 = ffma2(y23, x23, C.x);
        y01 = ffma2(y01, x01, D.y); y23 = ffma2(y23, x23, D.y);
        y01 = ffma2(y01, x01, D.x); y23 = ffma2(y23, x23, D.x);

        A = A2; B = B2; C = C2; D = D2;
    }

    // Peeled final group (coeffs 7..0) — no prefetch, no OOB reads
    y01 = ffma2(y01, x01, A.y); y23 = ffma2(y23, x23, A.y);
    y01 = ffma2(y01, x01, A.x); y23 = ffma2(y23, x23, A.x);
    y01 = ffma2(y01, x01, B.y); y23 = ffma2(y23, x23, B.y);
    y01 = ffma2(y01, x01, B.x); y23 = ffma2(y23, x23, B.x);
    y01 = ffma2(y01, x01, C.y); y23 = ffma2(y23, x23, C.y);
    y01 = ffma2(y01, x01, C.x); y23 = ffma2(y23, x23, C.x);
    y01 = ffma2(y01, x01, D.y); y23 = ffma2(y23, x23, D.y);
    y01 = ffma2(y01, x01, D.x); y23 = ffma2(y23, x23, D.x);

    float r0, r1, r2, r3;
    asm("mov.b64 {%0, %1}, %2;" : "=f"(r0), "=f"(r1) : "l"(y01));
    asm("mov.b64 {%0, %1}, %2;" : "=f"(r2), "=f"(r3) : "l"(y23));
    reinterpret_cast<float4*>(out)[t] = make_float4(r0, r1, r2, r3);
}

extern "C" void kernel_launch(void* const* d_in, const int* in_sizes, int n_in,
                              void* d_out, int out_size) {
    const float* x = (const float*)d_in[0];   // (512, 1024) fp32
    const float* w = (const float*)d_in[1];   // (1001,) fp32
    float* out = (float*)d_out;               // (512, 1024) fp32

    const int n4 = out_size / ELEMS_PER_THREAD;   // 131072 threads
    const int grid = n4 / THREADS_PER_BLOCK;      // 1024 blocks
    poly_horner_kernel<<<grid, THREADS_PER_BLOCK>>>(x, w, out);
}